// round 14
// baseline (speedup 1.0000x reference)
#include <cuda_runtime.h>
#include <cuda_bf16.h>
#include <math.h>

#define B_   32
#define T_   512
#define H_   1024
#define G4   4096   // 4*H

#define NCTA      128
#define NTHREADS  512

// ---------------------------------------------------------------------------
// Persistent device scratch (no cudaMalloc allowed)
// ---------------------------------------------------------------------------
__device__ float g_xz[(size_t)B_ * T_ * G4];        // [B*T, 4H] input projection
__device__ __nv_bfloat16 g_hbf[2][B_ * H_];         // double-buffered hidden (bf16)
__device__ unsigned g_flags[NCTA * 8];              // one stamp per CTA, 32B stride

// ---------------------------------------------------------------------------
// helpers
// ---------------------------------------------------------------------------
__device__ __forceinline__ void mma_bf16(float c[4],
                                         unsigned a0, unsigned a1, unsigned a2, unsigned a3,
                                         unsigned b0, unsigned b1) {
    asm volatile(
        "mma.sync.aligned.m16n8k16.row.col.f32.bf16.bf16.f32 "
        "{%0,%1,%2,%3}, {%4,%5,%6,%7}, {%8,%9}, {%0,%1,%2,%3};"
        : "+f"(c[0]), "+f"(c[1]), "+f"(c[2]), "+f"(c[3])
        : "r"(a0), "r"(a1), "r"(a2), "r"(a3), "r"(b0), "r"(b1));
}

__device__ __forceinline__ unsigned pack_bf16(float lo, float hi) {
    __nv_bfloat162 v = __floats2bfloat162_rn(lo, hi);
    return *(unsigned*)&v;
}

__device__ __forceinline__ float sigf(float v) {
    return __fdividef(1.0f, 1.0f + __expf(-v));
}
__device__ __forceinline__ float tanh_fast(float v) {
    return __fdividef(2.0f, 1.0f + __expf(-2.0f * v)) - 1.0f;
}

__device__ __forceinline__ void cp16(unsigned dst_smem, const void* src) {
    asm volatile("cp.async.cg.shared.global [%0], [%1], 16;"
                 :: "r"(dst_smem), "l"(src));
}

__device__ __forceinline__ unsigned ld_acq(const unsigned* p) {
    unsigned v;
    asm volatile("ld.acquire.gpu.global.b32 %0, [%1];" : "=r"(v) : "l"(p));
    return v;
}
__device__ __forceinline__ void st_rel(unsigned* p, unsigned v) {
    asm volatile("st.release.gpu.global.b32 [%0], %1;" :: "l"(p), "r"(v));
}

// ---------------------------------------------------------------------------
// Kernel 1: xz = x @ W + b  via bf16 m16n8k16 (CTA(0,0) re-inits state).
// ---------------------------------------------------------------------------
#define AS32_STRIDE 12
#define BS32_STRIDE 68

__global__ __launch_bounds__(256) void xw_gemm(const float* __restrict__ X,
                                               const float* __restrict__ W,
                                               const float* __restrict__ bias) {
    __shared__ unsigned As32[64 * AS32_STRIDE];
    __shared__ unsigned Bs32[8 * BS32_STRIDE];

    const int tid   = threadIdx.x;
    const int lane  = tid & 31;
    const int w     = tid >> 5;
    const int g     = lane >> 2;
    const int tig   = lane & 3;
    const int warpM = w >> 2;
    const int warpN = w & 3;

    // ---- per-replay state re-init ----
    if (blockIdx.x == 0 && blockIdx.y == 0) {
        unsigned* hz = (unsigned*)g_hbf[0];
        for (int i = tid; i < (B_ * H_) / 2; i += 256) hz[i] = 0u;
        for (int i = tid; i < NCTA * 8; i += 256) g_flags[i] = 0u;
    }

    const int row0 = blockIdx.y * 64;
    const int col0 = blockIdx.x * 64;

    const int aRow = tid >> 2;
    const int aC   = tid & 3;
    const int bKp  = tid >> 4;
    const int bNq  = tid & 15;

    float acc[2][2][4];
#pragma unroll
    for (int i = 0; i < 2; i++)
#pragma unroll
        for (int j = 0; j < 2; j++)
#pragma unroll
            for (int k = 0; k < 4; k++) acc[i][j][k] = 0.0f;

    for (int k0 = 0; k0 < H_; k0 += 16) {
        {
            float4 av = *(const float4*)(X + (size_t)(row0 + aRow) * H_ + k0 + 4 * aC);
            uint2 p;
            p.x = pack_bf16(av.x, av.y);
            p.y = pack_bf16(av.z, av.w);
            *(uint2*)(As32 + aRow * AS32_STRIDE + 2 * aC) = p;
        }
        if (tid < 128) {
            const float* wr0 = W + (size_t)(k0 + 2 * bKp)     * G4 + col0 + 4 * bNq;
            const float* wr1 = W + (size_t)(k0 + 2 * bKp + 1) * G4 + col0 + 4 * bNq;
            float4 w0 = *(const float4*)wr0;
            float4 w1 = *(const float4*)wr1;
            uint4 p;
            p.x = pack_bf16(w0.x, w1.x);
            p.y = pack_bf16(w0.y, w1.y);
            p.z = pack_bf16(w0.z, w1.z);
            p.w = pack_bf16(w0.w, w1.w);
            *(uint4*)(Bs32 + bKp * BS32_STRIDE + 4 * bNq) = p;
        }
        __syncthreads();

        unsigned a[2][4];
#pragma unroll
        for (int mi = 0; mi < 2; mi++) {
            const int r = warpM * 32 + mi * 16 + g;
            a[mi][0] = As32[r * AS32_STRIDE + tig];
            a[mi][1] = As32[(r + 8) * AS32_STRIDE + tig];
            a[mi][2] = As32[r * AS32_STRIDE + tig + 4];
            a[mi][3] = As32[(r + 8) * AS32_STRIDE + tig + 4];
        }
#pragma unroll
        for (int ni = 0; ni < 2; ni++) {
            const int n = warpN * 16 + ni * 8 + g;
            unsigned b0 = Bs32[tig * BS32_STRIDE + n];
            unsigned b1 = Bs32[(tig + 4) * BS32_STRIDE + n];
#pragma unroll
            for (int mi = 0; mi < 2; mi++)
                mma_bf16(acc[mi][ni], a[mi][0], a[mi][1], a[mi][2], a[mi][3], b0, b1);
        }
        __syncthreads();
    }

#pragma unroll
    for (int mi = 0; mi < 2; mi++) {
#pragma unroll
        for (int ni = 0; ni < 2; ni++) {
            int row = row0 + warpM * 32 + mi * 16 + g;
            int col = col0 + warpN * 16 + ni * 8 + 2 * tig;
            float2 bvv = *(const float2*)(bias + col);
            float2 v0 = make_float2(acc[mi][ni][0] + bvv.x, acc[mi][ni][1] + bvv.y);
            float2 v1 = make_float2(acc[mi][ni][2] + bvv.x, acc[mi][ni][3] + bvv.y);
            *(float2*)(g_xz + (size_t)row * G4 + col)       = v0;
            *(float2*)(g_xz + (size_t)(row + 8) * G4 + col) = v1;
        }
    }
}

// ---------------------------------------------------------------------------
// Kernel 2: persistent LSTM recurrence.
// R14: warp (ks,nh) polls only its 4 producer CTAs (k sub-range
// ks*128+nh*64 .. +64) and stages their pieces PIPELINED: poll flag p ->
// cp.async piece p (512B) -> poll p+1 (overlaps piece p in flight).
// Both warps of the ks-pair stage in parallel (2KB each), join at named bar.
// Rest identical to R13: MMA -> STS partials -> sync1 -> gates (warps 0-7)
// -> sync2 -> tid0 single-flag publish -> out store + prefetch.
// ---------------------------------------------------------------------------
#define HS_STRIDE  1032                    // bf16 per row (1024 + 8 pad)
#define RED_STRIDE 80                      // floats; conflict-free gate reads
#define HS_BYTES   (16 * HS_STRIDE * 2)
#define RED_BYTES  (128 * RED_STRIDE * 4)
#define SMEM_BYTES (HS_BYTES + RED_BYTES)

__global__ __launch_bounds__(NTHREADS, 1) void lstm_persistent(
        const float* __restrict__ U,
        const float* __restrict__ x,
        float* __restrict__ out) {
    extern __shared__ char smem[];
    __nv_bfloat16* hS = (__nv_bfloat16*)smem;          // [16][HS_STRIDE]
    float*        redS = (float*)(smem + HS_BYTES);    // [128][RED_STRIDE]

    const int tid  = threadIdx.x;
    const int lane = tid & 31;
    const int w    = tid >> 5;
    const int ks   = w & 7;       // k-slice (128 rows)
    const int nh   = w >> 3;      // n-half (32 cols) + k sub-half for staging
    const int g    = lane >> 2;
    const int tig  = lane & 3;

    const int half = blockIdx.x >> 6;
    const int dgrp = blockIdx.x & 63;
    const int d0   = dgrp * 16;
    const int bb   = half * 16;

    // this warp's 4 producer flags: CTAs half*64 + ks*8 + nh*4 + p
    const unsigned* pflags[4];
#pragma unroll
    for (int p = 0; p < 4; p++)
        pflags[p] = &g_flags[(half * 64 + ks * 8 + nh * 4 + p) * 8];

    // staging geometry: piece p = 16 rows x 16 k (32B/row); lane -> (row, chunk)
    const int srow = lane >> 1;           // 0..15
    const int schk = lane & 1;            // 0..1 (16B chunks)
    const int kwbase = ks * 128 + nh * 64;

    // ---- preload U fragments: warp covers n cols nh*32 + ng*8 + g ----
    unsigned breg[8][4][2];
#pragma unroll
    for (int kk = 0; kk < 8; kk++) {
#pragma unroll
        for (int ng = 0; ng < 4; ng++) {
            const int j    = nh * 32 + ng * 8 + g;
            const int ucol = (j >> 4) * H_ + d0 + (j & 15);
            const int k0   = ks * 128 + kk * 16 + 2 * tig;
            breg[kk][ng][0] = pack_bf16(U[(size_t)(k0    ) * G4 + ucol],
                                        U[(size_t)(k0 + 1) * G4 + ucol]);
            breg[kk][ng][1] = pack_bf16(U[(size_t)(k0 + 8) * G4 + ucol],
                                        U[(size_t)(k0 + 9) * G4 + ucol]);
        }
    }

    const int ebl = tid >> 4;    // local batch (gate phase, tid<256)
    const int ed  = tid & 15;    // local dim
    float c_reg = 0.0f;

    float zin[4];
    size_t xi = 0;
    float xres = 0.0f;
    if (tid < 256) {
#pragma unroll
        for (int gate = 0; gate < 4; gate++)
            zin[gate] = __ldcg(&g_xz[((size_t)(bb + ebl) * T_ + 0) * G4 + gate * H_ + d0 + ed]);
        xi = ((size_t)(bb + ebl) * T_ + 0) * H_ + d0 + ed;
        xres = __ldcg(&x[xi]);
    }

    for (int t = 0; t < T_; t++) {
        const unsigned need = (unsigned)t;
        const __nv_bfloat16* hprev = g_hbf[t & 1];
        __nv_bfloat16*       hcur  = g_hbf[(t + 1) & 1];

        // ---- pipelined poll+stage: piece p ready -> cp.async -> poll p+1 ----
#pragma unroll
        for (int p = 0; p < 4; p++) {
            while (ld_acq(pflags[p]) < need) { }
            const int kofs = kwbase + p * 16 + schk * 8;   // bf16 units
            cp16((unsigned)__cvta_generic_to_shared(hS + srow * HS_STRIDE + kofs),
                 hprev + (size_t)(bb + srow) * H_ + kofs);
        }
        asm volatile("cp.async.commit_group;");
        asm volatile("cp.async.wait_group 0;" ::: "memory");

        // pair join: both warps staged their k sub-halves
        asm volatile("bar.sync %0, %1;" :: "r"(ks + 1), "r"(64) : "memory");

        // ---- z partials: [16 x 32] over 128-k slice ----
        float acc[4][4];
#pragma unroll
        for (int ng = 0; ng < 4; ng++)
#pragma unroll
            for (int q = 0; q < 4; q++) acc[ng][q] = 0.0f;

#pragma unroll
        for (int kk = 0; kk < 8; kk++) {
            const int kcol = ks * 128 + kk * 16 + 2 * tig;
            const __nv_bfloat16* r0 = hS + g * HS_STRIDE;
            const __nv_bfloat16* r1 = hS + (g + 8) * HS_STRIDE;
            unsigned a0 = *(const unsigned*)(r0 + kcol);
            unsigned a1 = *(const unsigned*)(r1 + kcol);
            unsigned a2 = *(const unsigned*)(r0 + kcol + 8);
            unsigned a3 = *(const unsigned*)(r1 + kcol + 8);
#pragma unroll
            for (int ng = 0; ng < 4; ng++)
                mma_bf16(acc[ng], a0, a1, a2, a3, breg[kk][ng][0], breg[kk][ng][1]);
        }

        // ---- write k-partials ----
#pragma unroll
        for (int ng = 0; ng < 4; ng++) {
            const int col = nh * 32 + ng * 8 + 2 * tig;
            float* r0 = redS + (ks * 16 + g)     * RED_STRIDE + col;
            float* r1 = redS + (ks * 16 + g + 8) * RED_STRIDE + col;
            *(float2*)r0 = make_float2(acc[ng][0], acc[ng][1]);
            *(float2*)r1 = make_float2(acc[ng][2], acc[ng][3]);
        }
        __syncthreads();                                   // sync#1

        // ---- gates + state (warps 0-7) ----
        if (tid < 256) {
            const float* rb = redS + ebl * RED_STRIDE + ed;
            float z[4];
#pragma unroll
            for (int gate = 0; gate < 4; gate++) {
                const float* p = rb + gate * 16;
                float s = zin[gate];
#pragma unroll
                for (int q = 0; q < 8; q++) s += p[q * 16 * RED_STRIDE];
                z[gate] = s;
            }
            float ig = sigf(z[0]);
            float fg = sigf(z[1]);
            float gg = tanh_fast(z[2]);
            float og = sigf(z[3]);

            c_reg = fg * c_reg + ig * gg;
            float hn = og * tanh_fast(c_reg);
            __stcg(&hcur[(size_t)(bb + ebl) * H_ + d0 + ed], __float2bfloat16(hn));
            xres = tanh_fast(hn + xres);     // final output value (stored below)
        }
        __syncthreads();                                   // sync#2

        // ---- publish CTA stamp (cumulative release covers all h stores) ----
        if (tid == 0) st_rel(&g_flags[blockIdx.x * 8], (unsigned)(t + 1));

        // ---- off-critical-path: out store + next prefetch ----
        if (tid < 256) {
            out[xi] = xres;
            if (t + 1 < T_) {
#pragma unroll
                for (int gate = 0; gate < 4; gate++)
                    zin[gate] = __ldcg(&g_xz[((size_t)(bb + ebl) * T_ + t + 1) * G4 + gate * H_ + d0 + ed]);
                xi = ((size_t)(bb + ebl) * T_ + t + 1) * H_ + d0 + ed;
                xres = __ldcg(&x[xi]);
            }
        }
        // no third sync: all next-step STS paths pass sync#2 (directly, or
        // via named bar whose partner passed sync#2)
    }
}

// ---------------------------------------------------------------------------
extern "C" void kernel_launch(void* const* d_in, const int* in_sizes, int n_in,
                              void* d_out, int out_size) {
    const float* x    = (const float*)d_in[0];
    const float* W    = (const float*)d_in[1];
    const float* U    = (const float*)d_in[2];
    const float* bias = (const float*)d_in[3];
    float* out        = (float*)d_out;

    cudaFuncSetAttribute(lstm_persistent,
                         cudaFuncAttributeMaxDynamicSharedMemorySize, SMEM_BYTES);

    dim3 grid_gemm(G4 / 64, (B_ * T_) / 64);   // (64, 256)
    xw_gemm<<<grid_gemm, 256>>>(x, W, bias);

    lstm_persistent<<<NCTA, NTHREADS, SMEM_BYTES>>>(U, x, out);
}

// round 15
// speedup vs baseline: 1.3428x; 1.3428x over previous
#include <cuda_runtime.h>
#include <cuda_bf16.h>
#include <math.h>

#define B_   32
#define T_   512
#define H_   1024
#define G4   4096   // 4*H

#define NCTA      128
#define NTHREADS  512

// ---------------------------------------------------------------------------
// Persistent device scratch (no cudaMalloc allowed)
// ---------------------------------------------------------------------------
__device__ float g_xz[(size_t)B_ * T_ * G4];        // [B*T, 4H] input projection
__device__ __nv_bfloat16 g_hbf[2][B_ * H_];         // double-buffered hidden (bf16)
__device__ unsigned g_flags[NCTA * 8];              // one stamp per CTA, 32B stride

// ---------------------------------------------------------------------------
// helpers
// ---------------------------------------------------------------------------
__device__ __forceinline__ void mma_bf16(float c[4],
                                         unsigned a0, unsigned a1, unsigned a2, unsigned a3,
                                         unsigned b0, unsigned b1) {
    asm volatile(
        "mma.sync.aligned.m16n8k16.row.col.f32.bf16.bf16.f32 "
        "{%0,%1,%2,%3}, {%4,%5,%6,%7}, {%8,%9}, {%0,%1,%2,%3};"
        : "+f"(c[0]), "+f"(c[1]), "+f"(c[2]), "+f"(c[3])
        : "r"(a0), "r"(a1), "r"(a2), "r"(a3), "r"(b0), "r"(b1));
}

__device__ __forceinline__ unsigned pack_bf16(float lo, float hi) {
    __nv_bfloat162 v = __floats2bfloat162_rn(lo, hi);
    return *(unsigned*)&v;
}

__device__ __forceinline__ float sigf(float v) {
    return __fdividef(1.0f, 1.0f + __expf(-v));
}
__device__ __forceinline__ float tanh_fast(float v) {
    return __fdividef(2.0f, 1.0f + __expf(-2.0f * v)) - 1.0f;
}

__device__ __forceinline__ void cp16(unsigned dst_smem, const void* src) {
    asm volatile("cp.async.cg.shared.global [%0], [%1], 16;"
                 :: "r"(dst_smem), "l"(src));
}

__device__ __forceinline__ unsigned ld_acq(const unsigned* p) {
    unsigned v;
    asm volatile("ld.acquire.gpu.global.b32 %0, [%1];" : "=r"(v) : "l"(p));
    return v;
}
__device__ __forceinline__ void st_rel(unsigned* p, unsigned v) {
    asm volatile("st.release.gpu.global.b32 [%0], %1;" :: "l"(p), "r"(v));
}

// ---------------------------------------------------------------------------
// Kernel 1: xz = x @ W + b  via bf16 m16n8k16.  128x128 CTA tile, BK=16.
// 256 threads, 8 warps as 2(M)x4(N), warp tile 64x32 (4 mi x 4 ni).
// Halves L2 traffic vs the old 64x64 tiling (X read 32x instead of 64x,
// W 128x instead of 256x).  Conflict-free frag loads (A: stride 12,
// B: stride 136 -> tig*8+g is a 0..31 permutation).
// CTA(0,0) also re-inits recurrence state each replay.
// ---------------------------------------------------------------------------
#define AS32_STRIDE 12
#define BS32_STRIDE 136

__global__ __launch_bounds__(256) void xw_gemm(const float* __restrict__ X,
                                               const float* __restrict__ W,
                                               const float* __restrict__ bias) {
    __shared__ unsigned As32[128 * AS32_STRIDE];     // [row][kpair] 6KB
    __shared__ unsigned Bs32[8 * BS32_STRIDE];       // [kpair][n]   4.3KB

    const int tid   = threadIdx.x;
    const int lane  = tid & 31;
    const int w     = tid >> 5;
    const int g     = lane >> 2;
    const int tig   = lane & 3;
    const int warpM = w >> 2;      // 0..1  (64 rows each)
    const int warpN = w & 3;       // 0..3  (32 cols each)

    // ---- per-replay state re-init ----
    if (blockIdx.x == 0 && blockIdx.y == 0) {
        unsigned* hz = (unsigned*)g_hbf[0];
        for (int i = tid; i < (B_ * H_) / 2; i += 256) hz[i] = 0u;
        for (int i = tid; i < NCTA * 8; i += 256) g_flags[i] = 0u;
    }

    const int row0 = blockIdx.y * 128;
    const int col0 = blockIdx.x * 128;

    // staging maps
    const int aRow = tid >> 1;            // 0..127
    const int aH   = (tid & 1) * 8;       // k offset 0 or 8
    const int bKp  = tid >> 5;            // 0..7 (k pair row)
    const int bNq  = (tid & 31) * 4;      // 0..124 (n quad)

    float acc[4][4][4];
#pragma unroll
    for (int i = 0; i < 4; i++)
#pragma unroll
        for (int j = 0; j < 4; j++)
#pragma unroll
            for (int q = 0; q < 4; q++) acc[i][j][q] = 0.0f;

    for (int k0 = 0; k0 < H_; k0 += 16) {
        // stage A: 128 rows x 16 k (fp32 -> bf16 k-pairs); 8 floats/thread
        {
            const float* xr = X + (size_t)(row0 + aRow) * H_ + k0 + aH;
            float4 a0 = *(const float4*)xr;
            float4 a1 = *(const float4*)(xr + 4);
            uint4 p;
            p.x = pack_bf16(a0.x, a0.y);
            p.y = pack_bf16(a0.z, a0.w);
            p.z = pack_bf16(a1.x, a1.y);
            p.w = pack_bf16(a1.z, a1.w);
            *(uint4*)(As32 + aRow * AS32_STRIDE + aH / 2) = p;
        }
        // stage B: 16 k x 128 n (two k-rows packed per word); 8 floats/thread
        {
            const float* wr0 = W + (size_t)(k0 + 2 * bKp)     * G4 + col0 + bNq;
            const float* wr1 = W + (size_t)(k0 + 2 * bKp + 1) * G4 + col0 + bNq;
            float4 w0 = *(const float4*)wr0;
            float4 w1 = *(const float4*)wr1;
            uint4 p;
            p.x = pack_bf16(w0.x, w1.x);
            p.y = pack_bf16(w0.y, w1.y);
            p.z = pack_bf16(w0.z, w1.z);
            p.w = pack_bf16(w0.w, w1.w);
            *(uint4*)(Bs32 + bKp * BS32_STRIDE + bNq) = p;
        }
        __syncthreads();

        // A frags: 4 mi tiles (rows warpM*64 + mi*16 + {g, g+8})
        unsigned a[4][4];
#pragma unroll
        for (int mi = 0; mi < 4; mi++) {
            const int r = warpM * 64 + mi * 16 + g;
            a[mi][0] = As32[r * AS32_STRIDE + tig];
            a[mi][1] = As32[(r + 8) * AS32_STRIDE + tig];
            a[mi][2] = As32[r * AS32_STRIDE + tig + 4];
            a[mi][3] = As32[(r + 8) * AS32_STRIDE + tig + 4];
        }
        // B frags + MMAs: 4 ni groups
#pragma unroll
        for (int ni = 0; ni < 4; ni++) {
            const int n = warpN * 32 + ni * 8 + g;
            unsigned b0 = Bs32[tig * BS32_STRIDE + n];
            unsigned b1 = Bs32[(tig + 4) * BS32_STRIDE + n];
#pragma unroll
            for (int mi = 0; mi < 4; mi++)
                mma_bf16(acc[mi][ni], a[mi][0], a[mi][1], a[mi][2], a[mi][3], b0, b1);
        }
        __syncthreads();
    }

    // epilogue: + bias, store fp32
#pragma unroll
    for (int mi = 0; mi < 4; mi++) {
#pragma unroll
        for (int ni = 0; ni < 4; ni++) {
            int row = row0 + warpM * 64 + mi * 16 + g;
            int col = col0 + warpN * 32 + ni * 8 + 2 * tig;
            float2 bvv = *(const float2*)(bias + col);
            float2 v0 = make_float2(acc[mi][ni][0] + bvv.x, acc[mi][ni][1] + bvv.y);
            float2 v1 = make_float2(acc[mi][ni][2] + bvv.x, acc[mi][ni][3] + bvv.y);
            *(float2*)(g_xz + (size_t)row * G4 + col)       = v0;
            *(float2*)(g_xz + (size_t)(row + 8) * G4 + col) = v1;
        }
    }
}

// ---------------------------------------------------------------------------
// Kernel 2: persistent LSTM recurrence — EXACT R13 protocol (best verified:
// 2830us).  Batch-split halves, single CTA flag, low-traffic polling
// (only nh=0 warps poll 8 flags with 8 lanes; they stage the full slice).
// ---------------------------------------------------------------------------
#define HS_STRIDE  1032                    // bf16 per row (1024 + 8 pad)
#define RED_STRIDE 80                      // floats; conflict-free gate reads
#define HS_BYTES   (16 * HS_STRIDE * 2)
#define RED_BYTES  (128 * RED_STRIDE * 4)
#define SMEM_BYTES (HS_BYTES + RED_BYTES)

__global__ __launch_bounds__(NTHREADS, 1) void lstm_persistent(
        const float* __restrict__ U,
        const float* __restrict__ x,
        float* __restrict__ out) {
    extern __shared__ char smem[];
    __nv_bfloat16* hS = (__nv_bfloat16*)smem;          // [16][HS_STRIDE]
    float*        redS = (float*)(smem + HS_BYTES);    // [128][RED_STRIDE]

    const int tid  = threadIdx.x;
    const int lane = tid & 31;
    const int w    = tid >> 5;
    const int ks   = w & 7;       // k-slice (128 rows)
    const int nh   = w >> 3;      // n-half (32 cols)
    const int g    = lane >> 2;
    const int tig  = lane & 3;

    const int half = blockIdx.x >> 6;
    const int dgrp = blockIdx.x & 63;
    const int d0   = dgrp * 16;
    const int bb   = half * 16;

    // producer flag this lane polls (nh=0 warps, lanes 0..7)
    const unsigned* pflag = &g_flags[(half * 64 + 8 * ks + (lane & 7)) * 8];

    // ---- preload U fragments: warp covers n cols nh*32 + ng*8 + g ----
    unsigned breg[8][4][2];
#pragma unroll
    for (int kk = 0; kk < 8; kk++) {
#pragma unroll
        for (int ng = 0; ng < 4; ng++) {
            const int j    = nh * 32 + ng * 8 + g;
            const int ucol = (j >> 4) * H_ + d0 + (j & 15);
            const int k0   = ks * 128 + kk * 16 + 2 * tig;
            breg[kk][ng][0] = pack_bf16(U[(size_t)(k0    ) * G4 + ucol],
                                        U[(size_t)(k0 + 1) * G4 + ucol]);
            breg[kk][ng][1] = pack_bf16(U[(size_t)(k0 + 8) * G4 + ucol],
                                        U[(size_t)(k0 + 9) * G4 + ucol]);
        }
    }

    const int ebl = tid >> 4;    // local batch (gate phase, tid<256)
    const int ed  = tid & 15;    // local dim
    float c_reg = 0.0f;

    float zin[4];
    size_t xi = 0;
    float xres = 0.0f;
    if (tid < 256) {
#pragma unroll
        for (int gate = 0; gate < 4; gate++)
            zin[gate] = __ldcg(&g_xz[((size_t)(bb + ebl) * T_ + 0) * G4 + gate * H_ + d0 + ed]);
        xi = ((size_t)(bb + ebl) * T_ + 0) * H_ + d0 + ed;
        xres = __ldcg(&x[xi]);
    }

    for (int t = 0; t < T_; t++) {
        const unsigned need = (unsigned)t;
        const __nv_bfloat16* hprev = g_hbf[t & 1];
        __nv_bfloat16*       hcur  = g_hbf[(t + 1) & 1];

        if (nh == 0) {
            // ---- poll this warp's 8 producer CTA flags (lanes 0..7) ----
            for (;;) {
                bool ok = (lane >= 8) || (ld_acq(pflag) >= need);
                if (__all_sync(0xffffffffu, ok)) break;
            }
            // ---- stage full k-slice: 16 rows x 128 k (4KB), 8 cp16/lane ----
#pragma unroll
            for (int i = 0; i < 8; i++) {
                int q = i * 32 + lane;            // 0..255
                int r = q >> 4;                   // local batch row 0..15
                int c = q & 15;                   // 16B chunk in 256B row-slice
                cp16((unsigned)__cvta_generic_to_shared(hS + r * HS_STRIDE + ks * 128 + c * 8),
                     hprev + (size_t)(bb + r) * H_ + ks * 128 + c * 8);
            }
            asm volatile("cp.async.commit_group;");
            asm volatile("cp.async.wait_group 0;" ::: "memory");
        }
        // pair join: nh=1 waits here during poll+stage
        asm volatile("bar.sync %0, %1;" :: "r"(ks + 1), "r"(64) : "memory");

        // ---- z partials: [16 x 32] over 128-k slice ----
        float acc[4][4];
#pragma unroll
        for (int ng = 0; ng < 4; ng++)
#pragma unroll
            for (int q = 0; q < 4; q++) acc[ng][q] = 0.0f;

#pragma unroll
        for (int kk = 0; kk < 8; kk++) {
            const int kcol = ks * 128 + kk * 16 + 2 * tig;
            const __nv_bfloat16* r0 = hS + g * HS_STRIDE;
            const __nv_bfloat16* r1 = hS + (g + 8) * HS_STRIDE;
            unsigned a0 = *(const unsigned*)(r0 + kcol);
            unsigned a1 = *(const unsigned*)(r1 + kcol);
            unsigned a2 = *(const unsigned*)(r0 + kcol + 8);
            unsigned a3 = *(const unsigned*)(r1 + kcol + 8);
#pragma unroll
            for (int ng = 0; ng < 4; ng++)
                mma_bf16(acc[ng], a0, a1, a2, a3, breg[kk][ng][0], breg[kk][ng][1]);
        }

        // ---- write k-partials ----
#pragma unroll
        for (int ng = 0; ng < 4; ng++) {
            const int col = nh * 32 + ng * 8 + 2 * tig;
            float* r0 = redS + (ks * 16 + g)     * RED_STRIDE + col;
            float* r1 = redS + (ks * 16 + g + 8) * RED_STRIDE + col;
            *(float2*)r0 = make_float2(acc[ng][0], acc[ng][1]);
            *(float2*)r1 = make_float2(acc[ng][2], acc[ng][3]);
        }
        __syncthreads();                                   // sync#1

        // ---- gates + state (warps 0-7) ----
        if (tid < 256) {
            const float* rb = redS + ebl * RED_STRIDE + ed;
            float z[4];
#pragma unroll
            for (int gate = 0; gate < 4; gate++) {
                const float* p = rb + gate * 16;
                float s = zin[gate];
#pragma unroll
                for (int q = 0; q < 8; q++) s += p[q * 16 * RED_STRIDE];
                z[gate] = s;
            }
            float ig = sigf(z[0]);
            float fg = sigf(z[1]);
            float gg = tanh_fast(z[2]);
            float og = sigf(z[3]);

            c_reg = fg * c_reg + ig * gg;
            float hn = og * tanh_fast(c_reg);
            __stcg(&hcur[(size_t)(bb + ebl) * H_ + d0 + ed], __float2bfloat16(hn));
            xres = tanh_fast(hn + xres);     // final output value (stored below)
        }
        __syncthreads();                                   // sync#2

        // ---- publish CTA stamp (cumulative release covers all h stores) ----
        if (tid == 0) st_rel(&g_flags[blockIdx.x * 8], (unsigned)(t + 1));

        // ---- off-critical-path: out store + next prefetch ----
        if (tid < 256) {
            out[xi] = xres;
            if (t + 1 < T_) {
#pragma unroll
                for (int gate = 0; gate < 4; gate++)
                    zin[gate] = __ldcg(&g_xz[((size_t)(bb + ebl) * T_ + t + 1) * G4 + gate * H_ + d0 + ed]);
                xi = ((size_t)(bb + ebl) * T_ + t + 1) * H_ + d0 + ed;
                xres = __ldcg(&x[xi]);
            }
        }
        // no third sync: all next-step STS paths pass sync#2 (directly, or
        // via named bar whose partner passed sync#2)
    }
}

// ---------------------------------------------------------------------------
extern "C" void kernel_launch(void* const* d_in, const int* in_sizes, int n_in,
                              void* d_out, int out_size) {
    const float* x    = (const float*)d_in[0];
    const float* W    = (const float*)d_in[1];
    const float* U    = (const float*)d_in[2];
    const float* bias = (const float*)d_in[3];
    float* out        = (float*)d_out;

    cudaFuncSetAttribute(lstm_persistent,
                         cudaFuncAttributeMaxDynamicSharedMemorySize, SMEM_BYTES);

    dim3 grid_gemm(G4 / 128, (B_ * T_) / 128);   // (32, 128)
    xw_gemm<<<grid_gemm, 256>>>(x, W, bias);

    lstm_persistent<<<NCTA, NTHREADS, SMEM_BYTES>>>(U, x, out);
}